// round 5
// baseline (speedup 1.0000x reference)
#include <cuda_runtime.h>

#define NN    10000
#define NE    320000
#define HID   16
#define NL    7
#define KTOT  10000

// gemm1 tiling
#define TPB     128           // threads = rows per block
#define RPB     128
#define KS      16            // k per inner step (16 | 10000 -> no k guards)
#define SMAX    20            // steps per chunk
#define KC      (KS * SMAX)   // 320
#define NSPLIT  32            // covers 625 total steps
#define STAGES  4
#define APITCH  20            // floats per staged row (16B-aligned, odd 16B-unit stride)

// -------- scratch (no allocations allowed) --------
__device__ float g_deg_out[NN];
__device__ float g_deg_in[NN];
__device__ float g_norm_src[NN];
__device__ float g_norm_dst[NN];
__device__ float g_h[NN * HID];
__device__ float g_agg1[NN * HID];
__device__ float g_h2[NN * 8];
__device__ float g_agg2[NN * 8];
__device__ int   g_is64;

// -------- zero degree accumulators --------
__global__ void zero_kernel() {
    int i = blockIdx.x * blockDim.x + threadIdx.x;
    if (i < NN) { g_deg_out[i] = 0.f; g_deg_in[i] = 0.f; }
}

// -------- degrees (+ inline int64/int32 detection) --------
__global__ void degree_kernel(const int* __restrict__ src, const int* __restrict__ dst) {
    int is64 = ((src[1] | src[3] | src[5] | src[7] |
                 dst[1] | dst[3] | dst[5] | dst[7]) == 0) ? 1 : 0;
    int e = blockIdx.x * blockDim.x + threadIdx.x;
    if (e == 0) g_is64 = is64;
    if (e >= NE) return;
    int s = is64 ? src[2 * e] : src[e];
    int d = is64 ? dst[2 * e] : dst[e];
    atomicAdd(&g_deg_out[s], 1.f);
    atomicAdd(&g_deg_in[d], 1.f);
}

// -------- rsqrt norms + zero g_h / g_agg1 (both consumed after this kernel) --------
__global__ void norm_kernel() {
    int i = blockIdx.x * blockDim.x + threadIdx.x;
    if (i >= NN) return;
    g_norm_src[i] = rsqrtf(fmaxf(g_deg_out[i], 1.f));
    g_norm_dst[i] = rsqrtf(fmaxf(g_deg_in[i], 1.f));
    float4 z = make_float4(0.f, 0.f, 0.f, 0.f);
    float4* ph = reinterpret_cast<float4*>(&g_h[i * HID]);
    float4* pa = reinterpret_cast<float4*>(&g_agg1[i * HID]);
#pragma unroll
    for (int q = 0; q < 4; q++) { ph[q] = z; pa[q] = z; }
}

// -------- layer1 GEMM: 4-stage cp.async pipeline, broadcast-W compute --------
__global__ __launch_bounds__(TPB, 5) void gemm1_kernel(const float* __restrict__ A,
                                                       const float* __restrict__ W1) {
    __shared__ float As[STAGES][RPB * APITCH];   // 4 x 10240 B
    __shared__ float Ww[STAGES][KS * HID];       // 4 x 1024 B

    const int t  = threadIdx.x;
    const int r0 = blockIdx.x * RPB;
    const int k0 = blockIdx.y * KC;
    const int S  = min(SMAX, (KTOT - k0) / KS);  // >= 5 for every block

    const int srow = t >> 2;        // A staging: 4 segs of 16B per 64-float... (16 floats/row)
    const int sseg = t & 3;

    unsigned long long acc[8];
#pragma unroll
    for (int j = 0; j < 8; j++) acc[j] = 0ull;

    auto prefetch = [&](int s, int b) {
        const int kbase = k0 + s * KS;
        // A tile: 128 rows x 16 k = 512 float4; 4 per thread
        unsigned sA = (unsigned)__cvta_generic_to_shared(&As[b][srow * APITCH + sseg * 4]);
#pragma unroll
        for (int p = 0; p < 4; p++) {
            int gr = r0 + srow + 32 * p;
            bool ok = gr < NN;
            const void* gp = ok ? (const void*)(A + (size_t)gr * KTOT + kbase + sseg * 4)
                                : (const void*)A;
            int n = ok ? 16 : 0;
            asm volatile("cp.async.cg.shared.global [%0], [%1], 16, %2;"
                         :: "r"(sA + p * 32 * APITCH * 4), "l"(gp), "r"(n));
        }
        // W tile: 16 x 16 = 64 float4; threads 0..63
        if (t < 64) {
            int kw = t >> 2, u = t & 3;
            const void* gp = (const void*)(W1 + (size_t)(kbase + kw) * HID + u * 4);
            unsigned sW = (unsigned)__cvta_generic_to_shared(&Ww[b][kw * HID + u * 4]);
            asm volatile("cp.async.cg.shared.global [%0], [%1], 16, 16;"
                         :: "r"(sW), "l"(gp));
        }
        asm volatile("cp.async.commit_group;");
    };

    prefetch(0, 0);
    prefetch(1, 1);
    prefetch(2, 2);

    for (int s = 0; s < S; s++) {
        asm volatile("cp.async.wait_group 2;");
        __syncthreads();                     // stage s visible to all warps

        const float* as = &As[s & 3][t * APITCH];
        const float* wp = Ww[s & 3];
#pragma unroll
        for (int kq = 0; kq < KS / 4; kq++) {
            float4 a = *reinterpret_cast<const float4*>(as + kq * 4);
#pragma unroll
            for (int kk = 0; kk < 4; kk++) {
                float av = kk == 0 ? a.x : kk == 1 ? a.y : kk == 2 ? a.z : a.w;
                unsigned long long d;
                asm("mov.b64 %0, {%1, %1};" : "=l"(d) : "r"(__float_as_uint(av)));
                const ulonglong2* wr =
                    reinterpret_cast<const ulonglong2*>(wp + (kq * 4 + kk) * HID);
                ulonglong2 wa = wr[0], wb = wr[1], wc = wr[2], wd = wr[3];
                unsigned long long w[8] = {wa.x, wa.y, wb.x, wb.y, wc.x, wc.y, wd.x, wd.y};
#pragma unroll
                for (int j = 0; j < 8; j++) {
                    asm("fma.rn.f32x2 %0, %1, %2, %0;" : "+l"(acc[j]) : "l"(d), "l"(w[j]));
                }
            }
        }

        __syncthreads();                     // all warps done reading before reuse
        if (s + 3 < S) prefetch(s + 3, (s + 3) & 3);
    }

    const int r = r0 + t;
    if (r < NN) {
        float ns = g_norm_src[r];
#pragma unroll
        for (int j = 0; j < 8; j++) {
            float2 p = *reinterpret_cast<float2*>(&acc[j]);
            atomicAdd(&g_h[r * HID + 2 * j],     p.x * ns);
            atomicAdd(&g_h[r * HID + 2 * j + 1], p.y * ns);
        }
    }
}

// -------- edge scatter 1 (float4-vectorized): agg1[dst] += h[src] --------
__global__ void scatter1_kernel(const int* __restrict__ src, const int* __restrict__ dst) {
    int idx = blockIdx.x * blockDim.x + threadIdx.x;
    if (idx >= NE * 4) return;
    int e = idx >> 2, q = idx & 3;
    int is64 = g_is64;
    int s = is64 ? src[2 * e] : src[e];
    int d = is64 ? dst[2 * e] : dst[e];
    float4 v = *reinterpret_cast<const float4*>(&g_h[s * HID + q * 4]);
    float* o = &g_agg1[d * HID + q * 4];
    atomicAdd(o + 0, v.x); atomicAdd(o + 1, v.y);
    atomicAdd(o + 2, v.z); atomicAdd(o + 3, v.w);
}

// -------- relu + norm + layer2 GEMM (16x7), also zeroes agg2 --------
__global__ void act_gemm2_kernel(const float* __restrict__ b1, const float* __restrict__ W2) {
    __shared__ float W2s[HID * NL];
    __shared__ float b1s[HID];
    int t = threadIdx.x;
    if (t < HID * NL) W2s[t] = W2[t];
    if (t < HID) b1s[t] = b1[t];
    __syncthreads();
    int i = blockIdx.x * blockDim.x + t;
    if (i >= NN) return;
    *reinterpret_cast<float4*>(&g_agg2[i * 8])     = make_float4(0.f, 0.f, 0.f, 0.f);
    *reinterpret_cast<float4*>(&g_agg2[i * 8 + 4]) = make_float4(0.f, 0.f, 0.f, 0.f);

    float nd = g_norm_dst[i], ns = g_norm_src[i];
    float o[8];
#pragma unroll
    for (int l = 0; l < 8; l++) o[l] = 0.f;
    const float4* ag = (const float4*)(g_agg1 + i * HID);
#pragma unroll
    for (int q = 0; q < 4; q++) {
        float4 v = ag[q];
        float hv[4] = {v.x, v.y, v.z, v.w};
#pragma unroll
        for (int u = 0; u < 4; u++) {
            int j = q * 4 + u;
            float h1 = fmaxf(hv[u] * nd + b1s[j], 0.f) * ns;
#pragma unroll
            for (int l = 0; l < NL; l++) o[l] += h1 * W2s[j * NL + l];
        }
    }
    *reinterpret_cast<float4*>(&g_h2[i * 8])     = make_float4(o[0], o[1], o[2], o[3]);
    *reinterpret_cast<float4*>(&g_h2[i * 8 + 4]) = make_float4(o[4], o[5], o[6], 0.f);
}

// -------- edge scatter 2 (float4-vectorized, padded to 8 cols) --------
__global__ void scatter2_kernel(const int* __restrict__ src, const int* __restrict__ dst) {
    int idx = blockIdx.x * blockDim.x + threadIdx.x;
    if (idx >= NE * 2) return;
    int e = idx >> 1, q = idx & 1;
    int is64 = g_is64;
    int s = is64 ? src[2 * e] : src[e];
    int d = is64 ? dst[2 * e] : dst[e];
    float4 v = *reinterpret_cast<const float4*>(&g_h2[s * 8 + q * 4]);
    float* o = &g_agg2[d * 8 + q * 4];
    atomicAdd(o + 0, v.x); atomicAdd(o + 1, v.y);
    atomicAdd(o + 2, v.z); atomicAdd(o + 3, v.w);
}

// -------- epilogue: out = agg2 * norm_dst + b2 --------
__global__ void final_kernel(const float* __restrict__ b2, float* __restrict__ out) {
    int idx = blockIdx.x * blockDim.x + threadIdx.x;
    if (idx >= NN * NL) return;
    int i = idx / NL, l = idx - i * NL;
    out[idx] = g_agg2[i * 8 + l] * g_norm_dst[i] + __ldg(&b2[l]);
}

extern "C" void kernel_launch(void* const* d_in, const int* in_sizes, int n_in,
                              void* d_out, int out_size) {
    const float* features = (const float*)d_in[0];
    const int*   src      = (const int*)d_in[1];   // int32 or int64 (runtime-detected)
    const int*   dst      = (const int*)d_in[2];
    const float* W1       = (const float*)d_in[3];
    const float* b1       = (const float*)d_in[4];
    const float* W2       = (const float*)d_in[5];
    const float* b2       = (const float*)d_in[6];
    float* out = (float*)d_out;

    zero_kernel<<<(NN + 255) / 256, 256>>>();
    degree_kernel<<<(NE + 255) / 256, 256>>>(src, dst);
    norm_kernel<<<(NN + 255) / 256, 256>>>();
    gemm1_kernel<<<dim3((NN + RPB - 1) / RPB, NSPLIT), TPB>>>(features, W1);
    scatter1_kernel<<<(NE * 4 + 255) / 256, 256>>>(src, dst);
    act_gemm2_kernel<<<(NN + 255) / 256, 256>>>(b1, W2);
    scatter2_kernel<<<(NE * 2 + 255) / 256, 256>>>(src, dst);
    final_kernel<<<(NN * NL + 255) / 256, 256>>>(b2, out);
}